// round 8
// baseline (speedup 1.0000x reference)
#include <cuda_runtime.h>
#include <math.h>
#include <stdint.h>

#define BWIN   2048
#define NTOK   64
#define CDIM   256
#define MROWS  (BWIN * NTOK)
#define NBATCH 32
#define SCALE  0.0625f

// ---------------- scratch ----------------------------------------------------
// q/k/v/ao hold tf32 bit patterns (pre-converted by producers)
__device__ float g_q [MROWS * CDIM];
__device__ float g_k [MROWS * CDIM];
__device__ float g_v [MROWS * CDIM];
__device__ float g_ao[MROWS * CDIM];
__device__ float g_bias[NBATCH * NTOK * NTOK];
__device__ float g_wq [768 * CDIM];    // tf32(qkv_w)
__device__ float g_wp [CDIM * CDIM];   // tf32(proj_w)

// ---------------- helpers -----------------------------------------------------
__device__ __forceinline__ uint32_t f2tf(float f) {
    uint32_t u; asm("cvt.rna.tf32.f32 %0, %1;" : "=r"(u) : "f"(f)); return u;
}
__device__ __forceinline__ uint32_t u2tf(uint32_t x) {
    uint32_t u; asm("cvt.rna.tf32.f32 %0, %1;" : "=r"(u) : "f"(__uint_as_float(x))); return u;
}
__device__ __forceinline__ void mma8(float* c, uint32_t a0, uint32_t a1, uint32_t a2, uint32_t a3,
                                     uint32_t b0, uint32_t b1) {
    asm volatile(
        "mma.sync.aligned.m16n8k8.row.col.f32.tf32.tf32.f32 "
        "{%0,%1,%2,%3},{%4,%5,%6,%7},{%8,%9},{%0,%1,%2,%3};"
        : "+f"(c[0]), "+f"(c[1]), "+f"(c[2]), "+f"(c[3])
        : "r"(a0), "r"(a1), "r"(a2), "r"(a3), "r"(b0), "r"(b1));
}
__device__ __forceinline__ void ldsm4(uint32_t* r, const uint32_t* p) {
    uint32_t a = (uint32_t)__cvta_generic_to_shared(p);
    asm volatile("ldmatrix.sync.aligned.m8n8.x4.shared.b16 {%0,%1,%2,%3}, [%4];"
                 : "=r"(r[0]), "=r"(r[1]), "=r"(r[2]), "=r"(r[3]) : "r"(a));
}
__device__ __forceinline__ void cpasync16(uint32_t dst, const void* src) {
    asm volatile("cp.async.ca.shared.global [%0], [%1], 16;" :: "r"(dst), "l"(src));
}
__device__ __forceinline__ void cp_commit() { asm volatile("cp.async.commit_group;"); }
template <int N> __device__ __forceinline__ void cp_wait() {
    asm volatile("cp.async.wait_group %0;" :: "n"(N));
}

// ---------------- bias + weight tf32 precompute ---------------------------------
__global__ void bias_kernel(const float* __restrict__ theta_max,
                            const float* __restrict__ a_p, const float* __restrict__ b_p,
                            const float* __restrict__ a_r, const float* __restrict__ b_r,
                            const int*   __restrict__ radius,
                            const int*   __restrict__ azimuth)
{
    const int b = blockIdx.x;
    const float tm = theta_max[b];
    const float azc = 2.0f * 3.14159265358979323846f / 64.0f;
    for (int i = threadIdx.x; i < NTOK * NTOK; i += blockDim.x) {
        int az = azimuth[i];
        int ai = az < 0 ? az + 15 : az;
        float azf = (float)az * azc;
        float phi = a_p[ai] * cosf(azf) + b_p[ai] * sinf(azf);
        int r = radius[i];
        int ri = r < 0 ? r + 15 : r;
        float rn = (float)r * tm * (1.0f / 64.0f);
        float th = a_r[ri] * cosf(rn) + b_r[ri] * sinf(rn);
        g_bias[b * (NTOK * NTOK) + i] = phi + th;
    }
}

__global__ void wconv_kernel(const float* __restrict__ qkv_w, const float* __restrict__ proj_w)
{
    int i = blockIdx.x * blockDim.x + threadIdx.x;
    if (i < 768 * CDIM) g_wq[i] = __uint_as_float(f2tf(qkv_w[i]));
    if (i < CDIM * CDIM) g_wp[i] = __uint_as_float(f2tf(proj_w[i]));
}

// ---------------- tf32 GEMM: BM=128, BN=128, BK=32, 256 threads ----------------
// 8 warps (2M x 4N), warp tile 64x32. 2-stage cp.async. W side pre-converted.
// mode 0: A = x (fp32, cvt A frags), epilogue -> tf32 q/k/v.
// mode 1: A = g_ao (tf32 already), epilogue -> fp32 Cout.
#define AS_STRIDE 36
#define STG_WORDS (128 * AS_STRIDE)
#define GEMM_SMEM_WORDS (2 * 2 * STG_WORDS)

__global__ __launch_bounds__(256, 2)
void gemm_tf32_kernel(const float* __restrict__ A, const float* __restrict__ W,
                      const float* __restrict__ bias, float* __restrict__ Cout, int mode)
{
    extern __shared__ uint32_t smem[];
    uint32_t* As = smem;                   // [2][128*36]
    uint32_t* Ws = smem + 2 * STG_WORDS;   // [2][128*36]

    const int tid = threadIdx.x, lane = tid & 31, wid = tid >> 5;
    const int g = lane >> 2, tg = lane & 3;
    const int wm0 = (wid & 1) * 64, wn0 = (wid >> 1) * 32;
    const int m0 = blockIdx.y << 7, n0 = blockIdx.x << 7;

    const int lrA = (lane & 7) + ((lane >> 3) & 1) * 8;
    const int lkA = ((lane >> 4) & 1) * 4;
    const int lrB = (lane & 7) + ((lane >> 4) & 1) * 8;
    const int lkB = ((lane >> 3) & 1) * 4;

    const uint32_t sA = (uint32_t)__cvta_generic_to_shared(As);
    const uint32_t sW = (uint32_t)__cvta_generic_to_shared(Ws);

    uint32_t dOf[4]; size_t gAOf[4], gWOf[4];
#pragma unroll
    for (int i = 0; i < 4; i++) {
        int lin = tid + (i << 8); int r = lin >> 3, c = (lin & 7) << 2;
        dOf[i]  = (uint32_t)(r * AS_STRIDE + c) * 4;
        gAOf[i] = (size_t)(m0 + r) * 256 + c;
        gWOf[i] = (size_t)(n0 + r) * 256 + c;
    }

    float acc[4][4][4] = {};

#define ISSUE(s, k0)                                                   \
    do {                                                               \
        const int _k0 = (k0);                                          \
        uint32_t ob = (uint32_t)(s) * (STG_WORDS * 4);                 \
        _Pragma("unroll")                                              \
        for (int _ci = 0; _ci < 4; _ci++) {                            \
            cpasync16(sA + ob + dOf[_ci], A + gAOf[_ci] + _k0);        \
            cpasync16(sW + ob + dOf[_ci], W + gWOf[_ci] + _k0);        \
        }                                                              \
        cp_commit();                                                   \
    } while (0)

    ISSUE(0, 0);
    ISSUE(1, 32);

#pragma unroll
    for (int it = 0; it < 8; it++) {
        const int s = it & 1;
        if (it == 7) cp_wait<0>(); else cp_wait<1>();
        __syncthreads();

        const uint32_t* Ab = As + s * STG_WORDS;
        const uint32_t* Wb = Ws + s * STG_WORDS;
#pragma unroll
        for (int ks = 0; ks < 32; ks += 8) {
            uint32_t a[4][4], b[2][4];
#pragma unroll
            for (int mt = 0; mt < 4; mt++)
                ldsm4(a[mt], &Ab[(wm0 + mt * 16 + lrA) * AS_STRIDE + ks + lkA]);
#pragma unroll
            for (int p = 0; p < 2; p++)
                ldsm4(b[p], &Wb[(wn0 + p * 16 + lrB) * AS_STRIDE + ks + lkB]);
            if (mode == 0) {
#pragma unroll
                for (int mt = 0; mt < 4; mt++)
#pragma unroll
                    for (int j = 0; j < 4; j++) a[mt][j] = u2tf(a[mt][j]);
            }
#pragma unroll
            for (int mt = 0; mt < 4; mt++)
#pragma unroll
                for (int nt = 0; nt < 4; nt++) {
                    int p = nt >> 1, hi = (nt & 1) * 2;
                    mma8(acc[mt][nt], a[mt][0], a[mt][1], a[mt][2], a[mt][3], b[p][hi], b[p][hi + 1]);
                }
        }
        __syncthreads();
        if (it + 2 < 8) ISSUE(s, (it + 2) * 32);
    }
#undef ISSUE

    if (mode == 0) {
        float* buf; int off; float s;
        if (n0 < 256)      { buf = g_q; off = 0;   s = SCALE; }
        else if (n0 < 512) { buf = g_k; off = 256; s = 1.0f;  }
        else               { buf = g_v; off = 512; s = 1.0f;  }
#pragma unroll
        for (int mt = 0; mt < 4; mt++)
#pragma unroll
            for (int nt = 0; nt < 4; nt++) {
                int col = n0 + wn0 + nt * 8 + 2 * tg;
                float b0 = bias[col], b1 = bias[col + 1];
                int r = m0 + wm0 + mt * 16 + g;
                uint2 v0 = { f2tf((acc[mt][nt][0] + b0) * s), f2tf((acc[mt][nt][1] + b1) * s) };
                uint2 v1 = { f2tf((acc[mt][nt][2] + b0) * s), f2tf((acc[mt][nt][3] + b1) * s) };
                *(uint2*)(buf + (size_t)r * 256 + col - off)       = v0;
                *(uint2*)(buf + (size_t)(r + 8) * 256 + col - off) = v1;
            }
    } else {
#pragma unroll
        for (int mt = 0; mt < 4; mt++)
#pragma unroll
            for (int nt = 0; nt < 4; nt++) {
                int col = n0 + wn0 + nt * 8 + 2 * tg;
                float b0 = bias[col], b1 = bias[col + 1];
                int r = m0 + wm0 + mt * 16 + g;
                float2 v0 = { acc[mt][nt][0] + b0, acc[mt][nt][1] + b1 };
                float2 v1 = { acc[mt][nt][2] + b0, acc[mt][nt][3] + b1 };
                *(float2*)(Cout + (size_t)r * 256 + col)       = v0;
                *(float2*)(Cout + (size_t)(r + 8) * 256 + col) = v1;
            }
    }
}

// ---------------- fused per-window attention (inputs pre-converted) ------------
#define SS_STRIDE 68
#define VS_STRIDE 264
#define QS_STRIDE 36
#define ATTN_SMEM_WORDS (64 * VS_STRIDE + 64 * SS_STRIDE + 64 * QS_STRIDE * 2)

__global__ __launch_bounds__(256, 2)
void attn_mma_kernel()
{
    extern __shared__ uint32_t sm[];
    uint32_t* Vs = sm;
    uint32_t* Ss = Vs + 64 * VS_STRIDE;
    uint32_t* Qs = Ss + 64 * SS_STRIDE;
    uint32_t* Ks = Qs + 64 * QS_STRIDE;

    const int tid = threadIdx.x, lane = tid & 31, wid = tid >> 5;
    const int g = lane >> 2, tg = lane & 3;
    const int w = blockIdx.x;
    const size_t base = (size_t)w * NTOK * CDIM;

    const int lrA = (lane & 7) + ((lane >> 3) & 1) * 8;
    const int lkA = ((lane >> 4) & 1) * 4;
    const int lrB = (lane & 7) + ((lane >> 4) & 1) * 8;
    const int lkB = ((lane >> 3) & 1) * 4;

    // V (already tf32) -> smem, pass-through
#pragma unroll
    for (int i = 0; i < 16; i++) {
        int lin = tid + (i << 8); int r = lin >> 6, c = (lin & 63) << 2;
        uint4 v = *(const uint4*)((const uint32_t*)g_v + base + r * 256 + c);
        *(uint4*)&Vs[r * VS_STRIDE + c] = v;
    }

    const int wm0 = (wid & 3) * 16, wn0 = (wid >> 2) * 32;
    float acc1[4][4] = {};
    uint4 rq[2], rk[2];
#pragma unroll
    for (int i = 0; i < 2; i++) {
        int lin = tid + (i << 8); int r = lin >> 3, c = (lin & 7) << 2;
        rq[i] = *(const uint4*)((const uint32_t*)g_q + base + r * 256 + c);
        rk[i] = *(const uint4*)((const uint32_t*)g_k + base + r * 256 + c);
    }
    for (int k0 = 0; k0 < 256; k0 += 32) {
        __syncthreads();
#pragma unroll
        for (int i = 0; i < 2; i++) {
            int lin = tid + (i << 8); int r = lin >> 3, c = (lin & 7) << 2;
            *(uint4*)&Qs[r * QS_STRIDE + c] = rq[i];
            *(uint4*)&Ks[r * QS_STRIDE + c] = rk[i];
        }
        __syncthreads();
        if (k0 < 224) {
#pragma unroll
            for (int i = 0; i < 2; i++) {
                int lin = tid + (i << 8); int r = lin >> 3, c = (lin & 7) << 2;
                rq[i] = *(const uint4*)((const uint32_t*)g_q + base + r * 256 + k0 + 32 + c);
                rk[i] = *(const uint4*)((const uint32_t*)g_k + base + r * 256 + k0 + 32 + c);
            }
        }
#pragma unroll
        for (int ks = 0; ks < 32; ks += 8) {
            uint32_t a[4], b[2][4];
            ldsm4(a, &Qs[(wm0 + lrA) * QS_STRIDE + ks + lkA]);
#pragma unroll
            for (int p = 0; p < 2; p++)
                ldsm4(b[p], &Ks[(wn0 + p * 16 + lrB) * QS_STRIDE + ks + lkB]);
#pragma unroll
            for (int nt = 0; nt < 4; nt++) {
                int p = nt >> 1, hi = (nt & 1) * 2;
                mma8(acc1[nt], a[0], a[1], a[2], a[3], b[p][hi], b[p][hi + 1]);
            }
        }
    }

    {
        const float* bb = g_bias + (w >> 6) * (NTOK * NTOK);
        float* Sf = (float*)Ss;
#pragma unroll
        for (int nt = 0; nt < 4; nt++) {
            int col = wn0 + nt * 8 + 2 * tg;
            int r0 = wm0 + g;
            Sf[r0 * SS_STRIDE + col]           = acc1[nt][0] + bb[r0 * 64 + col];
            Sf[r0 * SS_STRIDE + col + 1]       = acc1[nt][1] + bb[r0 * 64 + col + 1];
            Sf[(r0 + 8) * SS_STRIDE + col]     = acc1[nt][2] + bb[(r0 + 8) * 64 + col];
            Sf[(r0 + 8) * SS_STRIDE + col + 1] = acc1[nt][3] + bb[(r0 + 8) * 64 + col + 1];
        }
    }
    __syncthreads();

    {
        float* Sf = (float*)Ss;
        int r = tid >> 2, p = tid & 3;
        float v[16];
        float mx = -1e30f;
#pragma unroll
        for (int i = 0; i < 16; i++) { v[i] = Sf[r * SS_STRIDE + p + 4 * i]; mx = fmaxf(mx, v[i]); }
        mx = fmaxf(mx, __shfl_xor_sync(0xffffffffu, mx, 1));
        mx = fmaxf(mx, __shfl_xor_sync(0xffffffffu, mx, 2));
        float s = 0.f;
#pragma unroll
        for (int i = 0; i < 16; i++) { v[i] = __expf(v[i] - mx); s += v[i]; }
        s += __shfl_xor_sync(0xffffffffu, s, 1);
        s += __shfl_xor_sync(0xffffffffu, s, 2);
        float inv = 1.0f / s;
#pragma unroll
        for (int i = 0; i < 16; i++) Ss[r * SS_STRIDE + p + 4 * i] = f2tf(v[i] * inv);
    }
    __syncthreads();

    {
        const int wn = wid * 32;
        float acc2[4][4][4] = {};
#pragma unroll
        for (int ks = 0; ks < 64; ks += 8) {
            uint32_t a[4][4];
#pragma unroll
            for (int mt = 0; mt < 4; mt++)
                ldsm4(a[mt], &Ss[(mt * 16 + lrA) * SS_STRIDE + ks + lkA]);
#pragma unroll
            for (int nt = 0; nt < 4; nt++) {
                uint32_t b0 = Vs[(ks + tg) * VS_STRIDE + wn + nt * 8 + g];
                uint32_t b1 = Vs[(ks + tg + 4) * VS_STRIDE + wn + nt * 8 + g];
#pragma unroll
                for (int mt = 0; mt < 4; mt++)
                    mma8(acc2[mt][nt], a[mt][0], a[mt][1], a[mt][2], a[mt][3], b0, b1);
            }
        }
        // store attention output pre-converted to tf32 (proj consumes as-is)
#pragma unroll
        for (int mt = 0; mt < 4; mt++)
#pragma unroll
            for (int nt = 0; nt < 4; nt++) {
                int col = wn + nt * 8 + 2 * tg, r0 = mt * 16 + g;
                uint2 v0 = { f2tf(acc2[mt][nt][0]), f2tf(acc2[mt][nt][1]) };
                uint2 v1 = { f2tf(acc2[mt][nt][2]), f2tf(acc2[mt][nt][3]) };
                *(uint2*)(g_ao + base + r0 * 256 + col)       = v0;
                *(uint2*)(g_ao + base + (r0 + 8) * 256 + col) = v1;
            }
    }
}

// ---------------- launch --------------------------------------------------------
extern "C" void kernel_launch(void* const* d_in, const int* in_sizes, int n_in,
                              void* d_out, int out_size)
{
    const float* x         = (const float*)d_in[0];
    const float* theta_max = (const float*)d_in[1];
    const float* qkv_w     = (const float*)d_in[2];
    const float* qkv_b     = (const float*)d_in[3];
    const float* proj_w    = (const float*)d_in[4];
    const float* proj_b    = (const float*)d_in[5];
    const float* a_p       = (const float*)d_in[6];
    const float* b_p       = (const float*)d_in[7];
    const float* a_r       = (const float*)d_in[8];
    const float* b_r       = (const float*)d_in[9];
    const int*   radius    = (const int*)d_in[10];
    const int*   azimuth   = (const int*)d_in[11];
    float*       out       = (float*)d_out;

    bias_kernel<<<NBATCH, 256>>>(theta_max, a_p, b_p, a_r, b_r, radius, azimuth);
    wconv_kernel<<<(768 * CDIM + 255) / 256, 256>>>(qkv_w, proj_w);

    float *g_ao_ptr = nullptr, *g_wq_ptr = nullptr, *g_wp_ptr = nullptr;
    cudaGetSymbolAddress((void**)&g_ao_ptr, g_ao);
    cudaGetSymbolAddress((void**)&g_wq_ptr, g_wq);
    cudaGetSymbolAddress((void**)&g_wp_ptr, g_wp);

    const int gemm_smem = GEMM_SMEM_WORDS * (int)sizeof(uint32_t);
    cudaFuncSetAttribute(gemm_tf32_kernel, cudaFuncAttributeMaxDynamicSharedMemorySize, gemm_smem);

    // qkv: [131072,256] x [256,768]
    gemm_tf32_kernel<<<dim3(768 / 128, MROWS / 128), 256, gemm_smem>>>(x, g_wq_ptr, qkv_b, nullptr, 0);

    // fused attention
    const int smem_bytes = ATTN_SMEM_WORDS * (int)sizeof(uint32_t);
    cudaFuncSetAttribute(attn_mma_kernel, cudaFuncAttributeMaxDynamicSharedMemorySize, smem_bytes);
    attn_mma_kernel<<<BWIN, 256, smem_bytes>>>();

    // proj: [131072,256] x [256,256]
    gemm_tf32_kernel<<<dim3(256 / 128, MROWS / 128), 256, gemm_smem>>>(g_ao_ptr, g_wp_ptr, proj_b, out, 1);
}

// round 9
// speedup vs baseline: 1.0374x; 1.0374x over previous
#include <cuda_runtime.h>
#include <math.h>
#include <stdint.h>

#define BWIN   2048
#define NTOK   64
#define CDIM   256
#define MROWS  (BWIN * NTOK)
#define NBATCH 32
#define SCALE  0.0625f

// ---------------- scratch ----------------------------------------------------
__device__ float g_q [MROWS * CDIM];
__device__ float g_k [MROWS * CDIM];
__device__ float g_v [MROWS * CDIM];
__device__ float g_ao[MROWS * CDIM];
__device__ float g_bias[NBATCH * NTOK * NTOK];
__device__ float g_wq [768 * CDIM];    // tf32(qkv_w)
__device__ float g_wp [CDIM * CDIM];   // tf32(proj_w)

// ---------------- helpers -----------------------------------------------------
__device__ __forceinline__ uint32_t f2tf(float f) {
    uint32_t u; asm("cvt.rna.tf32.f32 %0, %1;" : "=r"(u) : "f"(f)); return u;
}
__device__ __forceinline__ uint32_t u2tf(uint32_t x) {
    uint32_t u; asm("cvt.rna.tf32.f32 %0, %1;" : "=r"(u) : "f"(__uint_as_float(x))); return u;
}
__device__ __forceinline__ void mma8(float* c, uint32_t a0, uint32_t a1, uint32_t a2, uint32_t a3,
                                     uint32_t b0, uint32_t b1) {
    asm volatile(
        "mma.sync.aligned.m16n8k8.row.col.f32.tf32.tf32.f32 "
        "{%0,%1,%2,%3},{%4,%5,%6,%7},{%8,%9},{%0,%1,%2,%3};"
        : "+f"(c[0]), "+f"(c[1]), "+f"(c[2]), "+f"(c[3])
        : "r"(a0), "r"(a1), "r"(a2), "r"(a3), "r"(b0), "r"(b1));
}
__device__ __forceinline__ void ldsm4(uint32_t* r, const uint32_t* p) {
    uint32_t a = (uint32_t)__cvta_generic_to_shared(p);
    asm volatile("ldmatrix.sync.aligned.m8n8.x4.shared.b16 {%0,%1,%2,%3}, [%4];"
                 : "=r"(r[0]), "=r"(r[1]), "=r"(r[2]), "=r"(r[3]) : "r"(a));
}
__device__ __forceinline__ void cpasync16(uint32_t dst, const void* src) {
    asm volatile("cp.async.ca.shared.global [%0], [%1], 16;" :: "r"(dst), "l"(src));
}
__device__ __forceinline__ void cp_commit() { asm volatile("cp.async.commit_group;"); }
template <int N> __device__ __forceinline__ void cp_wait() {
    asm volatile("cp.async.wait_group %0;" :: "n"(N));
}

// ---------------- bias + weight tf32 precompute ---------------------------------
__global__ void bias_kernel(const float* __restrict__ theta_max,
                            const float* __restrict__ a_p, const float* __restrict__ b_p,
                            const float* __restrict__ a_r, const float* __restrict__ b_r,
                            const int*   __restrict__ radius,
                            const int*   __restrict__ azimuth)
{
    const int b = blockIdx.x;
    const float tm = theta_max[b];
    const float azc = 2.0f * 3.14159265358979323846f / 64.0f;
    for (int i = threadIdx.x; i < NTOK * NTOK; i += blockDim.x) {
        int az = azimuth[i];
        int ai = az < 0 ? az + 15 : az;
        float azf = (float)az * azc;
        float phi = a_p[ai] * cosf(azf) + b_p[ai] * sinf(azf);
        int r = radius[i];
        int ri = r < 0 ? r + 15 : r;
        float rn = (float)r * tm * (1.0f / 64.0f);
        float th = a_r[ri] * cosf(rn) + b_r[ri] * sinf(rn);
        g_bias[b * (NTOK * NTOK) + i] = phi + th;
    }
}

__global__ void wconv_kernel(const float* __restrict__ qkv_w, const float* __restrict__ proj_w)
{
    int i = blockIdx.x * blockDim.x + threadIdx.x;
    if (i < 768 * CDIM) g_wq[i] = __uint_as_float(f2tf(qkv_w[i]));
    if (i < CDIM * CDIM) g_wp[i] = __uint_as_float(f2tf(proj_w[i]));
}

// ---------------- tf32 GEMM: BM=128, BN=256, BK=32, 256 threads ----------------
// 8 warps (2M x 4N), warp tile 64x64. 2-stage cp.async.
#define AS_STRIDE 36
#define ASTG (128 * AS_STRIDE)
#define WSTG (256 * AS_STRIDE)
#define GEMM_SMEM_WORDS (2 * ASTG + 2 * WSTG)

__global__ __launch_bounds__(256)
void gemm_tf32_kernel(const float* __restrict__ A, const float* __restrict__ W,
                      const float* __restrict__ bias, float* __restrict__ Cout, int mode)
{
    extern __shared__ uint32_t smem[];
    uint32_t* As = smem;               // [2][128*36]
    uint32_t* Ws = smem + 2 * ASTG;    // [2][256*36]

    const int tid = threadIdx.x, lane = tid & 31, wid = tid >> 5;
    const int g = lane >> 2, tg = lane & 3;
    const int wm0 = (wid & 1) * 64, wn0 = (wid >> 1) * 64;
    const int m0 = blockIdx.y << 7, n0 = blockIdx.x << 8;

    const int lrA = (lane & 7) + ((lane >> 3) & 1) * 8;
    const int lkA = ((lane >> 4) & 1) * 4;
    const int lrB = (lane & 7) + ((lane >> 4) & 1) * 8;
    const int lkB = ((lane >> 3) & 1) * 4;

    const uint32_t sA = (uint32_t)__cvta_generic_to_shared(As);
    const uint32_t sW = (uint32_t)__cvta_generic_to_shared(Ws);

    // A: 1024 chunks (4/thread), W: 2048 chunks (8/thread)
    uint32_t dA[4]; size_t gA[4];
#pragma unroll
    for (int i = 0; i < 4; i++) {
        int lin = tid + (i << 8); int r = lin >> 3, c = (lin & 7) << 2;
        dA[i] = (uint32_t)(r * AS_STRIDE + c) * 4;
        gA[i] = (size_t)(m0 + r) * 256 + c;
    }
    uint32_t dW[8]; size_t gW[8];
#pragma unroll
    for (int i = 0; i < 8; i++) {
        int lin = tid + (i << 8); int r = lin >> 3, c = (lin & 7) << 2;
        dW[i] = (uint32_t)(r * AS_STRIDE + c) * 4;
        gW[i] = (size_t)(n0 + r) * 256 + c;
    }

    float acc[4][8][4] = {};

#define ISSUE(s, k0)                                                    \
    do {                                                                \
        const int _k0 = (k0);                                           \
        uint32_t obA = (uint32_t)(s) * (ASTG * 4);                      \
        uint32_t obW = (uint32_t)(s) * (WSTG * 4);                      \
        _Pragma("unroll")                                               \
        for (int _ci = 0; _ci < 4; _ci++)                               \
            cpasync16(sA + obA + dA[_ci], A + gA[_ci] + _k0);           \
        _Pragma("unroll")                                               \
        for (int _ci = 0; _ci < 8; _ci++)                               \
            cpasync16(sW + obW + dW[_ci], W + gW[_ci] + _k0);           \
        cp_commit();                                                    \
    } while (0)

    ISSUE(0, 0);
    ISSUE(1, 32);

#pragma unroll
    for (int it = 0; it < 8; it++) {
        const int s = it & 1;
        if (it == 7) cp_wait<0>(); else cp_wait<1>();
        __syncthreads();

        const uint32_t* Ab = As + s * ASTG;
        const uint32_t* Wb = Ws + s * WSTG;
#pragma unroll
        for (int ks = 0; ks < 32; ks += 8) {
            uint32_t a[4][4], b[4][4];
#pragma unroll
            for (int mt = 0; mt < 4; mt++)
                ldsm4(a[mt], &Ab[(wm0 + mt * 16 + lrA) * AS_STRIDE + ks + lkA]);
#pragma unroll
            for (int p = 0; p < 4; p++)
                ldsm4(b[p], &Wb[(wn0 + p * 16 + lrB) * AS_STRIDE + ks + lkB]);
            if (mode == 0) {
#pragma unroll
                for (int mt = 0; mt < 4; mt++)
#pragma unroll
                    for (int j = 0; j < 4; j++) a[mt][j] = u2tf(a[mt][j]);
            }
#pragma unroll
            for (int mt = 0; mt < 4; mt++)
#pragma unroll
                for (int nt = 0; nt < 8; nt++) {
                    int p = nt >> 1, hi = (nt & 1) * 2;
                    mma8(acc[mt][nt], a[mt][0], a[mt][1], a[mt][2], a[mt][3], b[p][hi], b[p][hi + 1]);
                }
        }
        __syncthreads();
        if (it + 2 < 8) ISSUE(s, (it + 2) * 32);
    }
#undef ISSUE

    if (mode == 0) {
        float* buf; float s;
        if (n0 == 0)        { buf = g_q; s = SCALE; }
        else if (n0 == 256) { buf = g_k; s = 1.0f;  }
        else                { buf = g_v; s = 1.0f;  }
#pragma unroll
        for (int mt = 0; mt < 4; mt++)
#pragma unroll
            for (int nt = 0; nt < 8; nt++) {
                int coln = wn0 + nt * 8 + 2 * tg;          // 0..255 within q/k/v
                float b0 = bias[n0 + coln], b1 = bias[n0 + coln + 1];
                int r = m0 + wm0 + mt * 16 + g;
                uint2 v0 = { f2tf((acc[mt][nt][0] + b0) * s), f2tf((acc[mt][nt][1] + b1) * s) };
                uint2 v1 = { f2tf((acc[mt][nt][2] + b0) * s), f2tf((acc[mt][nt][3] + b1) * s) };
                *(uint2*)(buf + (size_t)r * 256 + coln)       = v0;
                *(uint2*)(buf + (size_t)(r + 8) * 256 + coln) = v1;
            }
    } else {
#pragma unroll
        for (int mt = 0; mt < 4; mt++)
#pragma unroll
            for (int nt = 0; nt < 8; nt++) {
                int col = n0 + wn0 + nt * 8 + 2 * tg;
                float b0 = bias[col], b1 = bias[col + 1];
                int r = m0 + wm0 + mt * 16 + g;
                float2 v0 = { acc[mt][nt][0] + b0, acc[mt][nt][1] + b1 };
                float2 v1 = { acc[mt][nt][2] + b0, acc[mt][nt][3] + b1 };
                *(float2*)(Cout + (size_t)r * 256 + col)       = v0;
                *(float2*)(Cout + (size_t)(r + 8) * 256 + col) = v1;
            }
    }
}

// ---------------- fused per-window attention (unchanged from R8) ----------------
#define SS_STRIDE 68
#define VS_STRIDE 264
#define QS_STRIDE 36
#define ATTN_SMEM_WORDS (64 * VS_STRIDE + 64 * SS_STRIDE + 64 * QS_STRIDE * 2)

__global__ __launch_bounds__(256, 2)
void attn_mma_kernel()
{
    extern __shared__ uint32_t sm[];
    uint32_t* Vs = sm;
    uint32_t* Ss = Vs + 64 * VS_STRIDE;
    uint32_t* Qs = Ss + 64 * SS_STRIDE;
    uint32_t* Ks = Qs + 64 * QS_STRIDE;

    const int tid = threadIdx.x, lane = tid & 31, wid = tid >> 5;
    const int g = lane >> 2, tg = lane & 3;
    const int w = blockIdx.x;
    const size_t base = (size_t)w * NTOK * CDIM;

    const int lrA = (lane & 7) + ((lane >> 3) & 1) * 8;
    const int lkA = ((lane >> 4) & 1) * 4;
    const int lrB = (lane & 7) + ((lane >> 4) & 1) * 8;
    const int lkB = ((lane >> 3) & 1) * 4;

#pragma unroll
    for (int i = 0; i < 16; i++) {
        int lin = tid + (i << 8); int r = lin >> 6, c = (lin & 63) << 2;
        uint4 v = *(const uint4*)((const uint32_t*)g_v + base + r * 256 + c);
        *(uint4*)&Vs[r * VS_STRIDE + c] = v;
    }

    const int wm0 = (wid & 3) * 16, wn0 = (wid >> 2) * 32;
    float acc1[4][4] = {};
    uint4 rq[2], rk[2];
#pragma unroll
    for (int i = 0; i < 2; i++) {
        int lin = tid + (i << 8); int r = lin >> 3, c = (lin & 7) << 2;
        rq[i] = *(const uint4*)((const uint32_t*)g_q + base + r * 256 + c);
        rk[i] = *(const uint4*)((const uint32_t*)g_k + base + r * 256 + c);
    }
    for (int k0 = 0; k0 < 256; k0 += 32) {
        __syncthreads();
#pragma unroll
        for (int i = 0; i < 2; i++) {
            int lin = tid + (i << 8); int r = lin >> 3, c = (lin & 7) << 2;
            *(uint4*)&Qs[r * QS_STRIDE + c] = rq[i];
            *(uint4*)&Ks[r * QS_STRIDE + c] = rk[i];
        }
        __syncthreads();
        if (k0 < 224) {
#pragma unroll
            for (int i = 0; i < 2; i++) {
                int lin = tid + (i << 8); int r = lin >> 3, c = (lin & 7) << 2;
                rq[i] = *(const uint4*)((const uint32_t*)g_q + base + r * 256 + k0 + 32 + c);
                rk[i] = *(const uint4*)((const uint32_t*)g_k + base + r * 256 + k0 + 32 + c);
            }
        }
#pragma unroll
        for (int ks = 0; ks < 32; ks += 8) {
            uint32_t a[4], b[2][4];
            ldsm4(a, &Qs[(wm0 + lrA) * QS_STRIDE + ks + lkA]);
#pragma unroll
            for (int p = 0; p < 2; p++)
                ldsm4(b[p], &Ks[(wn0 + p * 16 + lrB) * QS_STRIDE + ks + lkB]);
#pragma unroll
            for (int nt = 0; nt < 4; nt++) {
                int p = nt >> 1, hi = (nt & 1) * 2;
                mma8(acc1[nt], a[0], a[1], a[2], a[3], b[p][hi], b[p][hi + 1]);
            }
        }
    }

    {
        const float* bb = g_bias + (w >> 6) * (NTOK * NTOK);
        float* Sf = (float*)Ss;
#pragma unroll
        for (int nt = 0; nt < 4; nt++) {
            int col = wn0 + nt * 8 + 2 * tg;
            int r0 = wm0 + g;
            Sf[r0 * SS_STRIDE + col]           = acc1[nt][0] + bb[r0 * 64 + col];
            Sf[r0 * SS_STRIDE + col + 1]       = acc1[nt][1] + bb[r0 * 64 + col + 1];
            Sf[(r0 + 8) * SS_STRIDE + col]     = acc1[nt][2] + bb[(r0 + 8) * 64 + col];
            Sf[(r0 + 8) * SS_STRIDE + col + 1] = acc1[nt][3] + bb[(r0 + 8) * 64 + col + 1];
        }
    }
    __syncthreads();

    {
        float* Sf = (float*)Ss;
        int r = tid >> 2, p = tid & 3;
        float v[16];
        float mx = -1e30f;
#pragma unroll
        for (int i = 0; i < 16; i++) { v[i] = Sf[r * SS_STRIDE + p + 4 * i]; mx = fmaxf(mx, v[i]); }
        mx = fmaxf(mx, __shfl_xor_sync(0xffffffffu, mx, 1));
        mx = fmaxf(mx, __shfl_xor_sync(0xffffffffu, mx, 2));
        float s = 0.f;
#pragma unroll
        for (int i = 0; i < 16; i++) { v[i] = __expf(v[i] - mx); s += v[i]; }
        s += __shfl_xor_sync(0xffffffffu, s, 1);
        s += __shfl_xor_sync(0xffffffffu, s, 2);
        float inv = 1.0f / s;
#pragma unroll
        for (int i = 0; i < 16; i++) Ss[r * SS_STRIDE + p + 4 * i] = f2tf(v[i] * inv);
    }
    __syncthreads();

    {
        const int wn = wid * 32;
        float acc2[4][4][4] = {};
#pragma unroll
        for (int ks = 0; ks < 64; ks += 8) {
            uint32_t a[4][4];
#pragma unroll
            for (int mt = 0; mt < 4; mt++)
                ldsm4(a[mt], &Ss[(mt * 16 + lrA) * SS_STRIDE + ks + lkA]);
#pragma unroll
            for (int nt = 0; nt < 4; nt++) {
                uint32_t b0 = Vs[(ks + tg) * VS_STRIDE + wn + nt * 8 + g];
                uint32_t b1 = Vs[(ks + tg + 4) * VS_STRIDE + wn + nt * 8 + g];
#pragma unroll
                for (int mt = 0; mt < 4; mt++)
                    mma8(acc2[mt][nt], a[mt][0], a[mt][1], a[mt][2], a[mt][3], b0, b1);
            }
        }
#pragma unroll
        for (int mt = 0; mt < 4; mt++)
#pragma unroll
            for (int nt = 0; nt < 4; nt++) {
                int col = wn + nt * 8 + 2 * tg, r0 = mt * 16 + g;
                uint2 v0 = { f2tf(acc2[mt][nt][0]), f2tf(acc2[mt][nt][1]) };
                uint2 v1 = { f2tf(acc2[mt][nt][2]), f2tf(acc2[mt][nt][3]) };
                *(uint2*)(g_ao + base + r0 * 256 + col)       = v0;
                *(uint2*)(g_ao + base + (r0 + 8) * 256 + col) = v1;
            }
    }
}

// ---------------- launch --------------------------------------------------------
extern "C" void kernel_launch(void* const* d_in, const int* in_sizes, int n_in,
                              void* d_out, int out_size)
{
    const float* x         = (const float*)d_in[0];
    const float* theta_max = (const float*)d_in[1];
    const float* qkv_w     = (const float*)d_in[2];
    const float* qkv_b     = (const float*)d_in[3];
    const float* proj_w    = (const float*)d_in[4];
    const float* proj_b    = (const float*)d_in[5];
    const float* a_p       = (const float*)d_in[6];
    const float* b_p       = (const float*)d_in[7];
    const float* a_r       = (const float*)d_in[8];
    const float* b_r       = (const float*)d_in[9];
    const int*   radius    = (const int*)d_in[10];
    const int*   azimuth   = (const int*)d_in[11];
    float*       out       = (float*)d_out;

    bias_kernel<<<NBATCH, 256>>>(theta_max, a_p, b_p, a_r, b_r, radius, azimuth);
    wconv_kernel<<<(768 * CDIM + 255) / 256, 256>>>(qkv_w, proj_w);

    float *g_ao_ptr = nullptr, *g_wq_ptr = nullptr, *g_wp_ptr = nullptr;
    cudaGetSymbolAddress((void**)&g_ao_ptr, g_ao);
    cudaGetSymbolAddress((void**)&g_wq_ptr, g_wq);
    cudaGetSymbolAddress((void**)&g_wp_ptr, g_wp);

    const int gemm_smem = GEMM_SMEM_WORDS * (int)sizeof(uint32_t);
    cudaFuncSetAttribute(gemm_tf32_kernel, cudaFuncAttributeMaxDynamicSharedMemorySize, gemm_smem);

    // qkv: [131072,256] x [256,768], BN=256 (one n-block per q/k/v)
    gemm_tf32_kernel<<<dim3(3, MROWS / 128), 256, gemm_smem>>>(x, g_wq_ptr, qkv_b, nullptr, 0);

    // fused attention
    const int smem_bytes = ATTN_SMEM_WORDS * (int)sizeof(uint32_t);
    cudaFuncSetAttribute(attn_mma_kernel, cudaFuncAttributeMaxDynamicSharedMemorySize, smem_bytes);
    attn_mma_kernel<<<BWIN, 256, smem_bytes>>>();

    // proj: [131072,256] x [256,256]
    gemm_tf32_kernel<<<dim3(1, MROWS / 128), 256, gemm_smem>>>(g_ao_ptr, g_wp_ptr, proj_b, out, 1);
}